// round 9
// baseline (speedup 1.0000x reference)
#include <cuda_runtime.h>

#define NT   1800          // total nodes (8*225)
#define NN   225
#define BB   8
#define HID  64
#define HA   32
#define NP   (NN*NN)       // 50625
#define PADJ 226
#define IGRP 5             // outer-nodes per pair-block (225 = 45*5)

// ---------------- scratch (device globals; zero-initialized at load) ----------------
__device__ float    g_agg0[NT*2];
__device__ float    g_h0a [NT*HID];
__device__ float    g_h0  [NT*HID];
__device__ float    g_agg1[NT*HID];
__device__ float    g_h1a [NT*HID];
__device__ float    g_feats[NT*HID];
__device__ float    g_bnsum0[HID], g_bnsq0[HID], g_bnsum1[HID], g_bnsq1[HID];
__device__ float    g_emb[BB*HID];
__device__ float    g_S  [BB*HA];
__device__ float    g_P1T[BB*HA*PADJ];   // [b][k][j], pad cols 225 stay 0 forever
__device__ float    g_P2 [NT*HA];        // [node][k]
__device__ float    g_L  [BB*NP];
__device__ unsigned g_maxu[BB];
__device__ float    g_sumexp[BB];
__device__ int      g_is64;              // 1 if edge_index delivered as int64

// ---------------- edge-index dtype detection ----------------
// int64 little-endian values in [0,1800): every odd 32-bit word is zero.
// int32 random indices: odd words are random nonzero values.
__global__ void k_detect(const unsigned* __restrict__ p, int nwords) {
    unsigned acc = 0;
    int lim = nwords < 256 ? nwords : 256;
    for (int i = 1; i < lim; i += 2) acc |= p[i];
    g_is64 = (acc == 0) ? 1 : 0;
}

__device__ __forceinline__ void load_edge(const void* ei, int e, int E, int& s, int& d) {
    if (g_is64) {
        const long long* p = (const long long*)ei;
        s = (int)p[e]; d = (int)p[E + e];
    } else {
        const int* p = (const int*)ei;
        s = p[e]; d = p[E + e];
    }
}

// ---------------- kernels ----------------
__global__ void k_zero() {
    int t = blockIdx.x*blockDim.x + threadIdx.x;
    int n = blockDim.x*gridDim.x;
    for (int i = t; i < NT*2;   i += n) g_agg0[i] = 0.f;
    for (int i = t; i < NT*HID; i += n) g_agg1[i] = 0.f;
    if (t < HID) { g_bnsum0[t]=0.f; g_bnsq0[t]=0.f; g_bnsum1[t]=0.f; g_bnsq1[t]=0.f; }
    if (t < BB)  { g_maxu[t]=0u; g_sumexp[t]=0.f; }
}

__global__ void k_scatter0(const float* __restrict__ x,
                           const void* __restrict__ ei, int E) {
    int e = blockIdx.x*blockDim.x + threadIdx.x;
    if (e >= E) return;
    int s, d; load_edge(ei, e, E, s, d);
    if ((unsigned)s >= NT || (unsigned)d >= NT) return;   // safety: never crash
    atomicAdd(&g_agg0[d*2+0], x[s*2+0]);
    atomicAdd(&g_agg0[d*2+1], x[s*2+1]);
}

// h0a = (x + agg0) @ g0_w1 + b1 ; accumulate BN sums
__global__ void k_lin0(const float* __restrict__ x,
                       const float* __restrict__ w1, const float* __restrict__ b1) {
    int rl = threadIdx.x >> 6, f = threadIdx.x & 63;
    int row = blockIdx.x*4 + rl;
    __shared__ float s_sum[HID], s_sq[HID];
    if (threadIdx.x < HID) { s_sum[threadIdx.x]=0.f; s_sq[threadIdx.x]=0.f; }
    __syncthreads();
    if (row < NT) {
        float t0 = x[row*2+0] + g_agg0[row*2+0];
        float t1 = x[row*2+1] + g_agg0[row*2+1];
        float h = b1[f] + t0*w1[f] + t1*w1[HID+f];
        g_h0a[row*HID+f] = h;
        atomicAdd(&s_sum[f], h);
        atomicAdd(&s_sq[f],  h*h);
    }
    __syncthreads();
    if (threadIdx.x < HID) {
        atomicAdd(&g_bnsum0[threadIdx.x], s_sum[threadIdx.x]);
        atomicAdd(&g_bnsq0 [threadIdx.x], s_sq [threadIdx.x]);
    }
}

// out = relu(BN(hin)) @ w2 + b2
__global__ void k_bnlin(int layer,
                        const float* __restrict__ gamma, const float* __restrict__ beta,
                        const float* __restrict__ w2, const float* __restrict__ b2) {
    const float* bnsum = layer ? g_bnsum1 : g_bnsum0;
    const float* bnsq  = layer ? g_bnsq1  : g_bnsq0;
    const float* hin   = layer ? g_h1a    : g_h0a;
    float*       outp  = layer ? g_feats  : g_h0;
    int rl = threadIdx.x >> 6, f = threadIdx.x & 63;
    int row = blockIdx.x*4 + rl;
    __shared__ float y[4][HID];
    float mean = bnsum[f] * (1.0f/NT);
    float var  = bnsq[f]  * (1.0f/NT) - mean*mean;
    float inv  = rsqrtf(var + 1e-5f) * gamma[f];
    if (row < NT) {
        float v = (hin[row*HID+f] - mean)*inv + beta[f];
        y[rl][f] = fmaxf(v, 0.f);
    }
    __syncthreads();
    if (row < NT) {
        float acc = b2[f];
        #pragma unroll
        for (int c = 0; c < HID; c++) acc = fmaf(y[rl][c], w2[c*HID+f], acc);
        outp[row*HID+f] = acc;
    }
}

// warp-per-edge scatter of 64-dim features
__global__ void k_scatter1(const void* __restrict__ ei, int E) {
    int gw   = (blockIdx.x*blockDim.x + threadIdx.x) >> 5;
    int lane = threadIdx.x & 31;
    if (gw >= E) return;
    int s, d; load_edge(ei, gw, E, s, d);
    if ((unsigned)s >= NT || (unsigned)d >= NT) return;
    atomicAdd(&g_agg1[d*HID + lane],      g_h0[s*HID + lane]);
    atomicAdd(&g_agg1[d*HID + lane + 32], g_h0[s*HID + lane + 32]);
}

// h1a = (h0 + agg1) @ g1_w1 + b1 ; accumulate BN sums
__global__ void k_lin1(const float* __restrict__ w1, const float* __restrict__ b1) {
    int rl = threadIdx.x >> 6, f = threadIdx.x & 63;
    int row = blockIdx.x*4 + rl;
    __shared__ float tin[4][HID];
    __shared__ float s_sum[HID], s_sq[HID];
    if (threadIdx.x < HID) { s_sum[threadIdx.x]=0.f; s_sq[threadIdx.x]=0.f; }
    if (row < NT) tin[rl][f] = g_h0[row*HID+f] + g_agg1[row*HID+f];
    __syncthreads();
    if (row < NT) {
        float acc = b1[f];
        #pragma unroll
        for (int c = 0; c < HID; c++) acc = fmaf(tin[rl][c], w1[c*HID+f], acc);
        g_h1a[row*HID+f] = acc;
        atomicAdd(&s_sum[f], acc);
        atomicAdd(&s_sq[f],  acc*acc);
    }
    __syncthreads();
    if (threadIdx.x < HID) {
        atomicAdd(&g_bnsum1[threadIdx.x], s_sum[threadIdx.x]);
        atomicAdd(&g_bnsq1 [threadIdx.x], s_sq [threadIdx.x]);
    }
}

// graph-mean pool + critic value + actor state-term S
__global__ void k_pool(const float* __restrict__ aw1, const float* __restrict__ ab1,
                       const float* __restrict__ cw1, const float* __restrict__ cb1,
                       const float* __restrict__ cw2, const float* __restrict__ cb2,
                       float* __restrict__ out_value) {
    int b = blockIdx.x, f = threadIdx.x;
    __shared__ float emb[HID];
    float s = 0.f;
    for (int r = 0; r < NN; r++) s += g_feats[(b*NN + r)*HID + f];
    emb[f] = s * (1.0f/NN);
    g_emb[b*HID + f] = emb[f];
    __syncthreads();
    if (f < HA) {
        float a = ab1[f], c = cb1[f];
        for (int cc = 0; cc < HID; cc++) {
            a = fmaf(emb[cc], aw1[cc*HA + f], a);   // a_w1 rows [0:64) = state block
            c = fmaf(emb[cc], cw1[cc*HA + f], c);
        }
        g_S[b*HA + f] = a;
        float hc = fmaxf(c, 0.f) * cw2[f];
        for (int o = 16; o > 0; o >>= 1) hc += __shfl_down_sync(0xffffffffu, hc, o);
        if (f == 0) out_value[b] = hc + cb2[0];
    }
}

// P1T[b][k][j] = feats_j @ a_w1[64:128] ; P2[node][k] = feats_i @ a_w1[128:192]
__global__ void k_pre(const float* __restrict__ aw1) {
    int n = blockIdx.x, t = threadIdx.x;
    __shared__ float row[HID];
    row[t] = g_feats[n*HID + t];
    __syncthreads();
    int k = t & 31, half = t >> 5;
    const float* w = aw1 + (half ? 128*HA : 64*HA);
    float acc = 0.f;
    #pragma unroll
    for (int c = 0; c < HID; c++) acc = fmaf(row[c], w[c*HA + k], acc);
    int b = n / NN, j = n % NN;
    if (half == 0) g_P1T[(b*HA + k)*PADJ + j] = acc;
    else           g_P2[n*HA + k] = acc;
}

// pair logits: 5 outer-nodes per block, P1 slab cached in shared; per-batch max via atomicMax
__global__ void k_pair(const float* __restrict__ aw2, const float* __restrict__ ab2) {
    __shared__ float P1s[HA*PADJ];     // 28928 B
    __shared__ float base[IGRP][HA];
    __shared__ float w2s[HA];
    __shared__ float red[256];
    int b  = blockIdx.x / (NN/IGRP);
    int i0 = (blockIdx.x % (NN/IGRP)) * IGRP;
    int t  = threadIdx.x;
    if (t < HA) w2s[t] = aw2[t];
    for (int idx = t; idx < HA*PADJ; idx += 256) P1s[idx] = g_P1T[b*HA*PADJ + idx];
    if (t < IGRP*HA) {
        int g = t >> 5, k = t & 31;
        base[g][k] = g_S[b*HA + k] + g_P2[(b*NN + i0 + g)*HA + k];
    }
    __syncthreads();
    float bias = ab2[0];
    float mx = -3.4e38f;
    int j = t;
    if (j < NN) {
        #pragma unroll
        for (int g = 0; g < IGRP; g++) {
            float acc = bias;
            #pragma unroll
            for (int k = 0; k < HA; k++) {
                float v = base[g][k] + P1s[k*PADJ + j];
                acc = fmaf(fmaxf(v, 0.f), w2s[k], acc);
            }
            g_L[b*NP + (i0 + g)*NN + j] = acc;
            mx = fmaxf(mx, acc);
        }
    }
    red[t] = mx; __syncthreads();
    for (int s = 128; s > 0; s >>= 1) { if (t < s) red[t] = fmaxf(red[t], red[t+s]); __syncthreads(); }
    if (t == 0) {
        unsigned u = __float_as_uint(red[0]);
        u = (u & 0x80000000u) ? ~u : (u | 0x80000000u);
        atomicMax(&g_maxu[b], u);
    }
}

__global__ void k_exp(float* __restrict__ pi) {
    int b = blockIdx.y;
    int idx = blockIdx.x*256 + threadIdx.x;
    __shared__ float red[256];
    unsigned u = g_maxu[b];
    float mx = (u & 0x80000000u) ? __uint_as_float(u & 0x7FFFFFFFu) : __uint_as_float(~u);
    float e = 0.f;
    if (idx < NP) {
        e = expf(g_L[b*NP + idx] - mx);
        pi[b*NP + idx] = e;
    }
    red[threadIdx.x] = e; __syncthreads();
    for (int s = 128; s > 0; s >>= 1) { if (threadIdx.x < s) red[threadIdx.x] += red[threadIdx.x+s]; __syncthreads(); }
    if (threadIdx.x == 0) atomicAdd(&g_sumexp[b], red[0]);
}

__global__ void k_norm(float* __restrict__ pi) {
    int b = blockIdx.y;
    int idx = blockIdx.x*256 + threadIdx.x;
    float r = 1.0f / g_sumexp[b];
    if (idx < NP) pi[b*NP + idx] *= r;
}

// ---------------- launcher ----------------
extern "C" void kernel_launch(void* const* d_in, const int* in_sizes, int n_in,
                              void* d_out, int out_size) {
    (void)n_in;
    const float* x   = (const float*)d_in[0];
    const void*  ei  = d_in[1];
    int E = in_sizes[1] / 2;
    const float* g0w1 = (const float*)d_in[3];
    const float* g0b1 = (const float*)d_in[4];
    const float* g0g  = (const float*)d_in[5];
    const float* g0be = (const float*)d_in[6];
    const float* g0w2 = (const float*)d_in[7];
    const float* g0b2 = (const float*)d_in[8];
    const float* g1w1 = (const float*)d_in[9];
    const float* g1b1 = (const float*)d_in[10];
    const float* g1g  = (const float*)d_in[11];
    const float* g1be = (const float*)d_in[12];
    const float* g1w2 = (const float*)d_in[13];
    const float* g1b2 = (const float*)d_in[14];
    const float* aw1  = (const float*)d_in[15];
    const float* ab1  = (const float*)d_in[16];
    const float* aw2  = (const float*)d_in[17];
    const float* ab2  = (const float*)d_in[18];
    const float* cw1  = (const float*)d_in[19];
    const float* cb1  = (const float*)d_in[20];
    const float* cw2  = (const float*)d_in[21];
    const float* cb2  = (const float*)d_in[22];

    float* out = (float*)d_out;
    float* pi  = out;                         // [8, 50625]
    float* val = out + BB*NP;                 // [8, 1]
    (void)out_size;

    k_detect  <<<1, 1>>>((const unsigned*)ei, in_sizes[1]);
    k_zero    <<<120, 256>>>();
    k_scatter0<<<(E + 255)/256, 256>>>(x, ei, E);
    k_lin0    <<<(NT + 3)/4, 256>>>(x, g0w1, g0b1);
    k_bnlin   <<<(NT + 3)/4, 256>>>(0, g0g, g0be, g0w2, g0b2);
    k_scatter1<<<(E*32 + 255)/256, 256>>>(ei, E);
    k_lin1    <<<(NT + 3)/4, 256>>>(g1w1, g1b1);
    k_bnlin   <<<(NT + 3)/4, 256>>>(1, g1g, g1be, g1w2, g1b2);
    k_pool    <<<BB, HID>>>(aw1, ab1, cw1, cb1, cw2, cb2, val);
    k_pre     <<<NT, HID>>>(aw1);
    k_pair    <<<BB*(NN/IGRP), 256>>>(aw2, ab2);
    dim3 gs((NP + 255)/256, BB);
    k_exp     <<<gs, 256>>>(pi);
    k_norm    <<<gs, 256>>>(pi);
}